// round 15
// baseline (speedup 1.0000x reference)
#include <cuda_runtime.h>
#include <cuda_bf16.h>
#include <cstdint>
#include <math_constants.h>

// Problem constants
#define PB 64
#define PL 196
#define PD 2048
#define PI 512
#define PM (PB * PL)   // 12544

// ---------------------------------------------------------------------------
// Scratch (__device__ globals; no cudaMalloc allowed)
// NOTE: softmax over l is shift-invariant => b_f, b_a, and the whole hidden-
// state path contribute only per-(b,d) constants to e and cancel in alpha/z.
// So we only need T = fv @ W_f and e = T @ W_a (no biases, no hs).
// ---------------------------------------------------------------------------
__device__ __align__(1024) __nv_bfloat16 g_Wft_hi[(size_t)PI * PD];  // W_f^T [512,2048]
__device__ __align__(1024) __nv_bfloat16 g_Wft_lo[(size_t)PI * PD];
__device__ __align__(1024) __nv_bfloat16 g_Wat_hi[(size_t)PD * PI];  // W_a^T [2048,512]
__device__ __align__(1024) __nv_bfloat16 g_Wat_lo[(size_t)PD * PI];
__device__ __align__(1024) __nv_bfloat16 g_T_hi[(size_t)PM * PI];
__device__ __align__(1024) __nv_bfloat16 g_T_lo[(size_t)PM * PI];

// ---------------------------------------------------------------------------
// Helpers (baseline ISA only: cp.async + mma.sync + ldmatrix)
// ---------------------------------------------------------------------------
__device__ __forceinline__ uint32_t smem_u32(const void* p) {
    uint32_t a;
    asm("{ .reg .u64 t; cvta.to.shared.u64 t, %1; cvt.u32.u64 %0, t; }" : "=r"(a) : "l"(p));
    return a;
}

#define CP_ASYNC16(dst, src) \
    asm volatile("cp.async.cg.shared.global [%0], [%1], 16;" :: "r"(dst), "l"(src))
#define CP_ASYNC_COMMIT() asm volatile("cp.async.commit_group;" ::: "memory")
#define CP_ASYNC_WAIT1() asm volatile("cp.async.wait_group 1;" ::: "memory")

__device__ __forceinline__ void ldsm_x4(uint32_t* r, uint32_t addr) {
    asm volatile(
        "ldmatrix.sync.aligned.m8n8.x4.shared.b16 {%0,%1,%2,%3}, [%4];"
        : "=r"(r[0]), "=r"(r[1]), "=r"(r[2]), "=r"(r[3]) : "r"(addr));
}

__device__ __forceinline__ void mma_bf16(float* c, const uint32_t* a, const uint32_t* b) {
    asm volatile(
        "mma.sync.aligned.m16n8k16.row.col.f32.bf16.bf16.f32 "
        "{%0,%1,%2,%3}, {%4,%5,%6,%7}, {%8,%9}, {%0,%1,%2,%3};"
        : "+f"(c[0]), "+f"(c[1]), "+f"(c[2]), "+f"(c[3])
        : "r"(a[0]), "r"(a[1]), "r"(a[2]), "r"(a[3]), "r"(b[0]), "r"(b[1]));
}

__device__ __forceinline__ void split2(float v, __nv_bfloat16& h, __nv_bfloat16& l) {
    h = __float2bfloat16(v);
    l = __float2bfloat16(v - __bfloat162float(h));
}

__device__ __forceinline__ uint32_t bf2_bits(__nv_bfloat16 a, __nv_bfloat16 b) {
    __nv_bfloat162 p(a, b);
    return *(uint32_t*)&p;
}

// ---------------------------------------------------------------------------
// Kernel: transpose [R?,C] -> [C,R], split to bf16 hi/lo  (out stride = R)
// ---------------------------------------------------------------------------
__global__ void tsplit_kernel(const float* __restrict__ in,
                              __nv_bfloat16* __restrict__ hi,
                              __nv_bfloat16* __restrict__ lo,
                              int R, int C) {
    __shared__ float tile[32][33];
    int r0 = blockIdx.y * 32, c0 = blockIdx.x * 32;
    int tx = threadIdx.x, ty = threadIdx.y;   // (32, 8)
#pragma unroll
    for (int j = 0; j < 32; j += 8)
        tile[ty + j][tx] = in[(size_t)(r0 + ty + j) * C + c0 + tx];
    __syncthreads();
#pragma unroll
    for (int j = 0; j < 32; j += 8) {
        float v = tile[tx][ty + j];
        __nv_bfloat16 h, l;
        split2(v, h, l);
        size_t o = (size_t)(c0 + ty + j) * R + r0 + tx;
        hi[o] = h; lo[o] = l;
    }
}

// ---------------------------------------------------------------------------
// GEMM1 (fused fp32->hi/lo conversion): T[m,n] = sum_k fv[m,k]*Wf[k,n]
// A = fv fp32 (converted in-kernel), B = Wft hi/lo bf16.
// BM=BN=128, BK=32, 3-stage cp.async ring, 256 threads (8 warps m64 x n32).
// Epilogue: split T -> g_T_hi/lo.
// ---------------------------------------------------------------------------
#define G1_K 2048
#define G1_NKT 64
#define G1_RSB 80                         // bf16 tile row stride bytes
#define G1_AF_B 16384                     // 128 rows x 32 fp32 = 16KB
#define G1_BT_B 10240                     // 128 rows x 80B
#define G1_STG_B (G1_AF_B + 2 * G1_BT_B)  // 36864
#define G1_AH_OFF (3 * G1_STG_B)          // 110592
#define G1_AL_OFF (G1_AH_OFF + G1_BT_B)   // 120832
#define G1_SMEM (G1_AL_OFF + G1_BT_B)     // 131072

__global__ __launch_bounds__(256) void gemm1_kernel(const float* __restrict__ fv) {
    extern __shared__ char smem[];
    const uint32_t sbase = smem_u32(smem);

    const int tid = threadIdx.x;
    const int wid = tid >> 5;
    const int lane = tid & 31;
    const int tq = lane >> 2;
    const int tp = lane & 3;
    const int m0 = (wid & 1) * 64;
    const int n0 = (wid >> 1) * 32;

    const uint32_t a_loff = (uint32_t)((lane & 15) * G1_RSB + ((lane >> 4) & 1) * 16);
    const uint32_t b_loff = (uint32_t)((((lane >> 4) & 1) * 8 + (lane & 7)) * G1_RSB +
                                       ((lane >> 3) & 1) * 16);

    const int rowBase = blockIdx.y * 128;
    const int colBase = blockIdx.x * 128;
    const float* A0 = fv + (size_t)rowBase * G1_K;
    const __nv_bfloat16* B0h = g_Wft_hi + (size_t)colBase * G1_K;
    const __nv_bfloat16* B0l = g_Wft_lo + (size_t)colBase * G1_K;

    float acc[4][4][4];
#pragma unroll
    for (int mi = 0; mi < 4; mi++)
#pragma unroll
        for (int ni = 0; ni < 4; ni++)
#pragma unroll
            for (int e = 0; e < 4; e++) acc[mi][ni][e] = 0.0f;

    auto load_stage = [&](int kt, int stg) {
        const uint32_t sb = sbase + stg * G1_STG_B;
        const int k0 = kt * 32;
        // A fp32: 1024 chunks of 16B, 4 per thread
#pragma unroll
        for (int i = 0; i < 4; i++) {
            const int idx = tid + i * 256;
            const int row = idx >> 3, ch = idx & 7;
            CP_ASYNC16(sb + (uint32_t)(row * 128 + ch * 16),
                       A0 + (size_t)row * G1_K + k0 + ch * 4);
        }
        // B hi/lo: 512 chunks each, 2 per thread
#pragma unroll
        for (int i = 0; i < 2; i++) {
            const int idx = tid + i * 256;
            const int row = idx >> 2, ch = idx & 3;
            const size_t ga = (size_t)row * G1_K + k0 + ch * 8;
            const uint32_t so = (uint32_t)(row * G1_RSB + ch * 16);
            CP_ASYNC16(sb + G1_AF_B + so,            B0h + ga);
            CP_ASYNC16(sb + G1_AF_B + G1_BT_B + so,  B0l + ga);
        }
        CP_ASYNC_COMMIT();
    };

    load_stage(0, 0);
    load_stage(1, 1);

    int stg_idx = 0;
    for (int kt = 0; kt < G1_NKT; kt++) {
        CP_ASYNC_WAIT1();
        __syncthreads();

        if (kt + 2 < G1_NKT) {
            int free_stg = stg_idx + 2;
            if (free_stg >= 3) free_stg -= 3;
            load_stage(kt + 2, free_stg);
        } else {
            CP_ASYNC_COMMIT();
        }

        const uint32_t sb = sbase + (uint32_t)stg_idx * G1_STG_B;

        // convert A fp32 stage -> Ah/Al (single buffer)
        {
            const float* Af = (const float*)(smem + (size_t)stg_idx * G1_STG_B);
#pragma unroll
            for (int j = 0; j < 4; j++) {
                const int f = tid + j * 256;        // float4 index 0..1023
                const int row = f >> 3, c4 = f & 7;
                float4 v = *(const float4*)(Af + f * 4);
                __nv_bfloat16 h0, h1, h2, h3, l0, l1, l2, l3;
                split2(v.x, h0, l0); split2(v.y, h1, l1);
                split2(v.z, h2, l2); split2(v.w, h3, l3);
                uint2 uh = {bf2_bits(h0, h1), bf2_bits(h2, h3)};
                uint2 ul = {bf2_bits(l0, l1), bf2_bits(l2, l3)};
                *(uint2*)(smem + G1_AH_OFF + row * G1_RSB + c4 * 8) = uh;
                *(uint2*)(smem + G1_AL_OFF + row * G1_RSB + c4 * 8) = ul;
            }
        }
        __syncthreads();

        const uint32_t aBaseH = sbase + G1_AH_OFF + (uint32_t)(m0 * G1_RSB) + a_loff;
        const uint32_t aBaseL = sbase + G1_AL_OFF + (uint32_t)(m0 * G1_RSB) + a_loff;
        const uint32_t bBaseH = sb + G1_AF_B + (uint32_t)(n0 * G1_RSB) + b_loff;
        const uint32_t bBaseL = bBaseH + G1_BT_B;

#pragma unroll
        for (int ks = 0; ks < 2; ks++) {
            const uint32_t ko = (uint32_t)(ks * 32);
            uint32_t ah[4][4], al[4][4], bh[2][4], bl[2][4];
#pragma unroll
            for (int mi = 0; mi < 4; mi++) {
                ldsm_x4(ah[mi], aBaseH + (uint32_t)(mi * 16 * G1_RSB) + ko);
                ldsm_x4(al[mi], aBaseL + (uint32_t)(mi * 16 * G1_RSB) + ko);
            }
#pragma unroll
            for (int p = 0; p < 2; p++) {
                ldsm_x4(bh[p], bBaseH + (uint32_t)(p * 16 * G1_RSB) + ko);
                ldsm_x4(bl[p], bBaseL + (uint32_t)(p * 16 * G1_RSB) + ko);
            }
#pragma unroll
            for (int mi = 0; mi < 4; mi++)
#pragma unroll
                for (int ni = 0; ni < 4; ni++) {
                    const uint32_t* bhf = &bh[ni >> 1][(ni & 1) * 2];
                    const uint32_t* blf = &bl[ni >> 1][(ni & 1) * 2];
                    mma_bf16(acc[mi][ni], ah[mi], bhf);
                    mma_bf16(acc[mi][ni], ah[mi], blf);
                    mma_bf16(acc[mi][ni], al[mi], bhf);
                }
        }
        __syncthreads();
        if (++stg_idx == 3) stg_idx = 0;
    }

    // epilogue: split T -> hi/lo (no bias, no hs)
#pragma unroll
    for (int mi = 0; mi < 4; mi++) {
        const int gr0 = rowBase + m0 + mi * 16 + tq;
        const int gr1 = gr0 + 8;
#pragma unroll
        for (int ni = 0; ni < 4; ni++) {
            const int gc = colBase + n0 + ni * 8 + tp * 2;
            __nv_bfloat16 h0, h1, h2, h3, l0, l1, l2, l3;
            split2(acc[mi][ni][0], h0, l0); split2(acc[mi][ni][1], h1, l1);
            split2(acc[mi][ni][2], h2, l2); split2(acc[mi][ni][3], h3, l3);
            const size_t o0 = ((size_t)gr0 * PI + gc) >> 1;
            const size_t o1 = ((size_t)gr1 * PI + gc) >> 1;
            ((__nv_bfloat162*)g_T_hi)[o0] = __nv_bfloat162(h0, h1);
            ((__nv_bfloat162*)g_T_lo)[o0] = __nv_bfloat162(l0, l1);
            ((__nv_bfloat162*)g_T_hi)[o1] = __nv_bfloat162(h2, h3);
            ((__nv_bfloat162*)g_T_lo)[o1] = __nv_bfloat162(l2, l3);
        }
    }
}

// ---------------------------------------------------------------------------
// Fused attention kernel: per CTA (b, 64-wide d-chunk)
//   e[196,64] = T[b] @ Wa chunk     (mma, hi/lo split; M padded to 208)
//   alpha = softmax over l; z = sum_l alpha * fv
// 416 threads = 13 warps; warp w owns m-rows [w*16, w*16+16).
// ---------------------------------------------------------------------------
#define AT_MP 208
#define AT_NW 13
#define AT_THREADS 416
#define AT_NKT 16                        // K=512 / 32
#define AT_AH 0
#define AT_AL 16640                      // 208*80
#define AT_BH 33280
#define AT_BL 38400                      // +64*80
#define AT_STG 43520
#define AT_SMEM (3 * AT_STG)             // 130560
#define AT_ERS 65                        // e row stride (floats), anti-conflict

__global__ __launch_bounds__(AT_THREADS) void attn_kernel(const float* __restrict__ fv,
                                                          float* __restrict__ z,
                                                          float* __restrict__ alpha) {
    extern __shared__ char smem[];
    const uint32_t sbase = smem_u32(smem);
    float* e_s   = (float*)smem;                             // [208][65]
    float* red   = (float*)(smem + AT_MP * AT_ERS * 4);      // [6][64]
    float* colv  = red + 6 * 64;                             // [64] max then reused
    float* colsum= colv + 64;                                // [64]

    const int tid = threadIdx.x;
    const int wid = tid >> 5;
    const int lane = tid & 31;
    const int tq = lane >> 2;
    const int tp = lane & 3;
    const int b = blockIdx.y;
    const int nchunk = blockIdx.x;
    const int dbase = nchunk * 64;

    const __nv_bfloat16* A0h = g_T_hi + (size_t)b * PL * PI;
    const __nv_bfloat16* A0l = g_T_lo + (size_t)b * PL * PI;
    const __nv_bfloat16* B0h = g_Wat_hi + (size_t)dbase * PI;
    const __nv_bfloat16* B0l = g_Wat_lo + (size_t)dbase * PI;

    const uint32_t a_loff = (uint32_t)((lane & 15) * G1_RSB + ((lane >> 4) & 1) * 16);
    const uint32_t b_loff = (uint32_t)((((lane >> 4) & 1) * 8 + (lane & 7)) * G1_RSB +
                                       ((lane >> 3) & 1) * 16);

    // zero pad rows 196..207 of Ah/Al in all 3 stages (loads never touch them)
    {
        // 12 rows * 80B * 2 matrices * 3 stages = 5760B = 360 uint4
        for (int i = tid; i < 360; i += AT_THREADS) {
            const int s = i / 120;            // stage
            const int r = i % 120;            // 120 uint4 per stage (2 matrices)
            const int mat = r / 60;           // 0=Ah, 1=Al
            const int off = (r % 60) * 16;    // 60 uint4 = 960B = 12 rows * 80B
            uint4 zz = {0, 0, 0, 0};
            *(uint4*)(smem + s * AT_STG + (mat ? AT_AL : AT_AH) + 196 * G1_RSB + off) = zz;
        }
    }

    float acc[8][4];
#pragma unroll
    for (int ni = 0; ni < 8; ni++)
#pragma unroll
        for (int e = 0; e < 4; e++) acc[ni][e] = 0.0f;

    auto load_stage = [&](int kt, int stg) {
        const uint32_t sb = sbase + stg * AT_STG;
        const int k0 = kt * 32;
        // A: 196 rows x 4 chunks = 784 per matrix
#pragma unroll
        for (int i = 0; i < 2; i++) {
            const int idx = tid + i * AT_THREADS;
            if (idx < 784) {
                const int row = idx >> 2, ch = idx & 3;
                const size_t ga = (size_t)row * PI + k0 + ch * 8;
                const uint32_t so = (uint32_t)(row * G1_RSB + ch * 16);
                CP_ASYNC16(sb + AT_AH + so, A0h + ga);
                CP_ASYNC16(sb + AT_AL + so, A0l + ga);
            }
        }
        // B: 64 rows x 4 chunks = 256
        if (tid < 256) {
            const int row = tid >> 2, ch = tid & 3;
            const size_t ga = (size_t)row * PI + k0 + ch * 8;
            const uint32_t so = (uint32_t)(row * G1_RSB + ch * 16);
            CP_ASYNC16(sb + AT_BH + so, B0h + ga);
            CP_ASYNC16(sb + AT_BL + so, B0l + ga);
        }
        CP_ASYNC_COMMIT();
    };

    load_stage(0, 0);
    load_stage(1, 1);

    int stg_idx = 0;
    for (int kt = 0; kt < AT_NKT; kt++) {
        CP_ASYNC_WAIT1();
        __syncthreads();

        if (kt + 2 < AT_NKT) {
            int free_stg = stg_idx + 2;
            if (free_stg >= 3) free_stg -= 3;
            load_stage(kt + 2, free_stg);
        } else {
            CP_ASYNC_COMMIT();
        }

        const uint32_t sb = sbase + (uint32_t)stg_idx * AT_STG;
        const uint32_t aBaseH = sb + AT_AH + (uint32_t)(wid * 16 * G1_RSB) + a_loff;
        const uint32_t aBaseL = sb + AT_AL + (uint32_t)(wid * 16 * G1_RSB) + a_loff;
        const uint32_t bBaseH = sb + AT_BH + b_loff;
        const uint32_t bBaseL = sb + AT_BL + b_loff;

#pragma unroll
        for (int ks = 0; ks < 2; ks++) {
            const uint32_t ko = (uint32_t)(ks * 32);
            uint32_t ah[4], al[4], bh[4][4], bl[4][4];
            ldsm_x4(ah, aBaseH + ko);
            ldsm_x4(al, aBaseL + ko);
#pragma unroll
            for (int p = 0; p < 4; p++) {
                ldsm_x4(bh[p], bBaseH + (uint32_t)(p * 16 * G1_RSB) + ko);
                ldsm_x4(bl[p], bBaseL + (uint32_t)(p * 16 * G1_RSB) + ko);
            }
#pragma unroll
            for (int ni = 0; ni < 8; ni++) {
                const uint32_t* bhf = &bh[ni >> 1][(ni & 1) * 2];
                const uint32_t* blf = &bl[ni >> 1][(ni & 1) * 2];
                mma_bf16(acc[ni], ah, bhf);
                mma_bf16(acc[ni], ah, blf);
                mma_bf16(acc[ni], al, bhf);
            }
        }
        __syncthreads();
        if (++stg_idx == 3) stg_idx = 0;
    }

    // store e to smem (rows >= 196 stored but never read)
    {
        const int r0 = wid * 16 + tq;
#pragma unroll
        for (int ni = 0; ni < 8; ni++) {
            const int c = ni * 8 + tp * 2;
            e_s[r0 * AT_ERS + c]           = acc[ni][0];
            e_s[r0 * AT_ERS + c + 1]       = acc[ni][1];
            e_s[(r0 + 8) * AT_ERS + c]     = acc[ni][2];
            e_s[(r0 + 8) * AT_ERS + c + 1] = acc[ni][3];
        }
    }
    __syncthreads();

    // column softmax over l (196 rows). 6 row-groups x 64 cols = 384 threads.
    const int c = tid & 63;
    const int rg = tid >> 6;           // 0..6 (6 = idle tail)
    const int r0 = rg * 33;
    const int rend = (r0 + 33 < PL) ? r0 + 33 : PL;

    if (rg < 6) {
        float m = -CUDART_INF_F;
        for (int r = r0; r < rend; r++) m = fmaxf(m, e_s[r * AT_ERS + c]);
        red[rg * 64 + c] = m;
    }
    __syncthreads();
    if (tid < 64) {
        float m = red[tid];
#pragma unroll
        for (int t = 1; t < 6; t++) m = fmaxf(m, red[t * 64 + tid]);
        colv[tid] = m;
    }
    __syncthreads();

    if (rg < 6) {
        const float cm = colv[c];
        float s = 0.0f;
        for (int r = r0; r < rend; r++) {
            float e = __expf(e_s[r * AT_ERS + c] - cm);
            e_s[r * AT_ERS + c] = e;
            s += e;
        }
        red[rg * 64 + c] = s;
    }
    __syncthreads();
    if (tid < 64) {
        float s = red[tid];
#pragma unroll
        for (int t = 1; t < 6; t++) s += red[t * 64 + tid];
        colsum[tid] = s;
    }
    __syncthreads();

    // alpha write + z partials
    if (rg < 6) {
        const float inv = 1.0f / colsum[c];
        const int gc = dbase + c;
        float zp = 0.0f;
        for (int r = r0; r < rend; r++) {
            const size_t ga = ((size_t)b * PL + r) * PD + gc;
            float a = e_s[r * AT_ERS + c] * inv;
            alpha[ga] = a;
            zp = fmaf(a, fv[ga], zp);
        }
        red[rg * 64 + c] = zp;
    }
    __syncthreads();
    if (tid < 64) {
        float s = red[tid];
#pragma unroll
        for (int t = 1; t < 6; t++) s += red[t * 64 + tid];
        z[(size_t)b * PD + dbase + tid] = s;
    }
}

// ---------------------------------------------------------------------------
// Launch
// ---------------------------------------------------------------------------
extern "C" void kernel_launch(void* const* d_in, const int* in_sizes, int n_in,
                              void* d_out, int out_size) {
    const float* fv     = (const float*)d_in[0];
    const float* W_f    = (const float*)d_in[2];
    const float* W_a    = (const float*)d_in[6];

    float* out   = (float*)d_out;
    float* z     = out;
    float* alpha = out + (size_t)PB * PD;

    cudaFuncSetAttribute(gemm1_kernel,
                         cudaFuncAttributeMaxDynamicSharedMemorySize, G1_SMEM);
    cudaFuncSetAttribute(attn_kernel,
                         cudaFuncAttributeMaxDynamicSharedMemorySize, AT_SMEM);

    __nv_bfloat16 *wft_hi, *wft_lo, *wat_hi, *wat_lo;
    cudaGetSymbolAddress((void**)&wft_hi, g_Wft_hi);
    cudaGetSymbolAddress((void**)&wft_lo, g_Wft_lo);
    cudaGetSymbolAddress((void**)&wat_hi, g_Wat_hi);
    cudaGetSymbolAddress((void**)&wat_lo, g_Wat_lo);

    // weight transpose + split
    tsplit_kernel<<<dim3(PI / 32, PD / 32), dim3(32, 8)>>>(W_f, wft_hi, wft_lo, PD, PI);
    tsplit_kernel<<<dim3(PD / 32, PI / 32), dim3(32, 8)>>>(W_a, wat_hi, wat_lo, PI, PD);

    // GEMM1: T = fv @ W_f  (M=12544, N=512, K=2048), fv converted in-kernel
    gemm1_kernel<<<dim3(PI / 128, PM / 128), 256, G1_SMEM>>>(fv);

    // fused: e = T @ W_a -> softmax -> alpha, z
    attn_kernel<<<dim3(PD / 64, PB), AT_THREADS, AT_SMEM>>>(fv, z, alpha);
}

// round 16
// speedup vs baseline: 1.1876x; 1.1876x over previous
#include <cuda_runtime.h>
#include <cuda_bf16.h>
#include <cstdint>
#include <math_constants.h>

// Problem constants
#define PB 64
#define PL 196
#define PD 2048
#define PI 512
#define PM (PB * PL)   // 12544

// ---------------------------------------------------------------------------
// Scratch (__device__ globals; no cudaMalloc allowed)
// NOTE: softmax over l is shift-invariant => b_f, b_a, and the whole hidden-
// state path contribute only per-(b,d) constants to e and cancel in alpha/z.
// So we only need T = fv @ W_f and E = T @ W_a (no biases, no hs).
// ---------------------------------------------------------------------------
__device__ __align__(1024) __nv_bfloat16 g_fv_hi[(size_t)PM * PD];
__device__ __align__(1024) __nv_bfloat16 g_fv_lo[(size_t)PM * PD];
__device__ __align__(1024) __nv_bfloat16 g_Wft_hi[(size_t)PI * PD];  // W_f^T [512,2048]
__device__ __align__(1024) __nv_bfloat16 g_Wft_lo[(size_t)PI * PD];
__device__ __align__(1024) __nv_bfloat16 g_Wat_hi[(size_t)PD * PI];  // W_a^T [2048,512]
__device__ __align__(1024) __nv_bfloat16 g_Wat_lo[(size_t)PD * PI];
__device__ __align__(1024) __nv_bfloat16 g_T_hi[(size_t)PM * PI];
__device__ __align__(1024) __nv_bfloat16 g_T_lo[(size_t)PM * PI];
__device__ __align__(1024) float g_E[(size_t)PM * PD];

// ---------------------------------------------------------------------------
// Helpers (baseline ISA only: cp.async + mma.sync + ldmatrix)
// ---------------------------------------------------------------------------
__device__ __forceinline__ uint32_t smem_u32(const void* p) {
    uint32_t a;
    asm("{ .reg .u64 t; cvta.to.shared.u64 t, %1; cvt.u32.u64 %0, t; }" : "=r"(a) : "l"(p));
    return a;
}

#define CP_ASYNC16(dst, src) \
    asm volatile("cp.async.cg.shared.global [%0], [%1], 16;" :: "r"(dst), "l"(src))
#define CP_ASYNC_COMMIT() asm volatile("cp.async.commit_group;" ::: "memory")
#define CP_ASYNC_WAIT1() asm volatile("cp.async.wait_group 1;" ::: "memory")

__device__ __forceinline__ void ldsm_x4(uint32_t* r, uint32_t addr) {
    asm volatile(
        "ldmatrix.sync.aligned.m8n8.x4.shared.b16 {%0,%1,%2,%3}, [%4];"
        : "=r"(r[0]), "=r"(r[1]), "=r"(r[2]), "=r"(r[3]) : "r"(addr));
}

__device__ __forceinline__ void mma_bf16(float* c, const uint32_t* a, const uint32_t* b) {
    asm volatile(
        "mma.sync.aligned.m16n8k16.row.col.f32.bf16.bf16.f32 "
        "{%0,%1,%2,%3}, {%4,%5,%6,%7}, {%8,%9}, {%0,%1,%2,%3};"
        : "+f"(c[0]), "+f"(c[1]), "+f"(c[2]), "+f"(c[3])
        : "r"(a[0]), "r"(a[1]), "r"(a[2]), "r"(a[3]), "r"(b[0]), "r"(b[1]));
}

__device__ __forceinline__ void split2(float v, __nv_bfloat16& h, __nv_bfloat16& l) {
    h = __float2bfloat16(v);
    l = __float2bfloat16(v - __bfloat162float(h));
}

// ---------------------------------------------------------------------------
// Kernel: split fv -> bf16 hi/lo
// ---------------------------------------------------------------------------
__global__ __launch_bounds__(256) void split_fv_kernel(const float* __restrict__ in) {
    size_t i = (size_t)blockIdx.x * blockDim.x + threadIdx.x;   // float4 index
    const size_t n4 = (size_t)PM * PD / 4;
    if (i >= n4) return;
    float4 v = ((const float4*)in)[i];
    __nv_bfloat16 h0, h1, h2, h3, l0, l1, l2, l3;
    split2(v.x, h0, l0); split2(v.y, h1, l1);
    split2(v.z, h2, l2); split2(v.w, h3, l3);
    __nv_bfloat162* ph = (__nv_bfloat162*)g_fv_hi;
    __nv_bfloat162* pl = (__nv_bfloat162*)g_fv_lo;
    ph[2 * i]     = __nv_bfloat162(h0, h1);
    ph[2 * i + 1] = __nv_bfloat162(h2, h3);
    pl[2 * i]     = __nv_bfloat162(l0, l1);
    pl[2 * i + 1] = __nv_bfloat162(l2, l3);
}

// ---------------------------------------------------------------------------
// Kernel: transpose [R?,C] -> [C,R], split to bf16 hi/lo  (out stride = R)
// ---------------------------------------------------------------------------
__global__ void tsplit_kernel(const float* __restrict__ in,
                              __nv_bfloat16* __restrict__ hi,
                              __nv_bfloat16* __restrict__ lo,
                              int R, int C) {
    __shared__ float tile[32][33];
    int r0 = blockIdx.y * 32, c0 = blockIdx.x * 32;
    int tx = threadIdx.x, ty = threadIdx.y;   // (32, 8)
#pragma unroll
    for (int j = 0; j < 32; j += 8)
        tile[ty + j][tx] = in[(size_t)(r0 + ty + j) * C + c0 + tx];
    __syncthreads();
#pragma unroll
    for (int j = 0; j < 32; j += 8) {
        float v = tile[tx][ty + j];
        __nv_bfloat16 h, l;
        split2(v, h, l);
        size_t o = (size_t)(c0 + ty + j) * R + r0 + tx;
        hi[o] = h; lo[o] = l;
    }
}

// ---------------------------------------------------------------------------
// mma.sync GEMM (bf16 3-MMA hi/lo split):  D[m,n] = sum_k A[m,k]*B[n,k]
// BM=BN=128, BK=32, 3-stage cp.async ring, 256 threads (8 warps, m64 x n32 each)
// Fragments via ldmatrix.x4 (stride 80B -> conflict-free).
// EPI1: split D -> g_T_hi/lo (bf16).   else: D -> g_E (fp32).
// ---------------------------------------------------------------------------
#define GK_BM 128
#define GK_BN 128
#define GK_BK 32
#define GK_RS 40                         // padded row stride (bf16 elements) = 80 bytes
#define GK_RSB 80
#define GK_TILE_B (GK_BM * GK_RSB)       // 10240 bytes
#define GK_STAGE_B (4 * GK_TILE_B)       // Ah, Al, Bh, Bl  = 40960
#define GK_STAGES 3
#define GEMM_SMEM (GK_STAGES * GK_STAGE_B)  // 122880

template<int NK, bool EPI1>
__global__ __launch_bounds__(256) void gemm_kernel() {
    constexpr int K = NK * GK_BK;
    extern __shared__ char smem[];
    const uint32_t sbase = smem_u32(smem);

    const int tid = threadIdx.x;
    const int wid = tid >> 5;
    const int lane = tid & 31;
    const int tq = lane >> 2;    // 0..7
    const int tp = lane & 3;     // 0..3
    const int m0 = (wid & 1) * 64;
    const int n0 = (wid >> 1) * 32;

    // ldmatrix per-lane byte offsets within a tile
    const uint32_t a_loff = (uint32_t)((lane & 15) * GK_RSB + ((lane >> 4) & 1) * 16);
    const uint32_t b_loff = (uint32_t)((((lane >> 4) & 1) * 8 + (lane & 7)) * GK_RSB +
                                       ((lane >> 3) & 1) * 16);

    const __nv_bfloat16* Agh = EPI1 ? g_fv_hi : g_T_hi;
    const __nv_bfloat16* Agl = EPI1 ? g_fv_lo : g_T_lo;
    const __nv_bfloat16* Bgh = EPI1 ? g_Wft_hi : g_Wat_hi;
    const __nv_bfloat16* Bgl = EPI1 ? g_Wft_lo : g_Wat_lo;

    const int rowBase = blockIdx.y * GK_BM;
    const int colBase = blockIdx.x * GK_BN;
    const __nv_bfloat16* A0h = Agh + (size_t)rowBase * K;
    const __nv_bfloat16* A0l = Agl + (size_t)rowBase * K;
    const __nv_bfloat16* B0h = Bgh + (size_t)colBase * K;
    const __nv_bfloat16* B0l = Bgl + (size_t)colBase * K;

    float acc[4][4][4];
#pragma unroll
    for (int mi = 0; mi < 4; mi++)
#pragma unroll
        for (int ni = 0; ni < 4; ni++)
#pragma unroll
            for (int e = 0; e < 4; e++) acc[mi][ni][e] = 0.0f;

    // load slots: 512 16B-chunks per tile (128 rows x 4), 2 per thread
    const int s0 = tid, s1 = tid + 256;
    const int r0_ = s0 >> 2, ch0 = s0 & 3;
    const int r1_ = s1 >> 2, ch1 = s1 & 3;
    const uint32_t so0 = (uint32_t)(r0_ * GK_RSB + ch0 * 16);
    const uint32_t so1 = (uint32_t)(r1_ * GK_RSB + ch1 * 16);

    auto load_stage = [&](int kt, int stg) {
        const uint32_t sb = sbase + stg * GK_STAGE_B;
        const int k0 = kt * GK_BK;
        {
            const size_t ga = (size_t)r0_ * K + k0 + ch0 * 8;
            CP_ASYNC16(sb + so0,                 A0h + ga);
            CP_ASYNC16(sb + GK_TILE_B + so0,     A0l + ga);
            CP_ASYNC16(sb + 2 * GK_TILE_B + so0, B0h + ga);
            CP_ASYNC16(sb + 3 * GK_TILE_B + so0, B0l + ga);
        }
        {
            const size_t ga = (size_t)r1_ * K + k0 + ch1 * 8;
            CP_ASYNC16(sb + so1,                 A0h + ga);
            CP_ASYNC16(sb + GK_TILE_B + so1,     A0l + ga);
            CP_ASYNC16(sb + 2 * GK_TILE_B + so1, B0h + ga);
            CP_ASYNC16(sb + 3 * GK_TILE_B + so1, B0l + ga);
        }
        CP_ASYNC_COMMIT();
    };

    // prologue: 2 stages in flight
    load_stage(0, 0);
    load_stage(1, 1);

    int stg_idx = 0;   // stage holding chunk kt
    for (int kt = 0; kt < NK; kt++) {
        CP_ASYNC_WAIT1();
        __syncthreads();

        if (kt + 2 < NK) {
            int free_stg = stg_idx + 2;
            if (free_stg >= GK_STAGES) free_stg -= GK_STAGES;
            load_stage(kt + 2, free_stg);
        } else {
            CP_ASYNC_COMMIT();   // empty group keeps wait_group accounting uniform
        }

        const uint32_t sb = sbase + (uint32_t)stg_idx * GK_STAGE_B;
        const uint32_t aBaseH = sb + (uint32_t)(m0 * GK_RSB) + a_loff;
        const uint32_t aBaseL = aBaseH + GK_TILE_B;
        const uint32_t bBaseH = sb + 2 * GK_TILE_B + (uint32_t)(n0 * GK_RSB) + b_loff;
        const uint32_t bBaseL = bBaseH + GK_TILE_B;

#pragma unroll
        for (int ks = 0; ks < 2; ks++) {
            const uint32_t ko = (uint32_t)(ks * 32);
            uint32_t ah[4][4], al[4][4], bh[2][4], bl[2][4];
#pragma unroll
            for (int mi = 0; mi < 4; mi++) {
                ldsm_x4(ah[mi], aBaseH + (uint32_t)(mi * 16 * GK_RSB) + ko);
                ldsm_x4(al[mi], aBaseL + (uint32_t)(mi * 16 * GK_RSB) + ko);
            }
#pragma unroll
            for (int p = 0; p < 2; p++) {
                ldsm_x4(bh[p], bBaseH + (uint32_t)(p * 16 * GK_RSB) + ko);
                ldsm_x4(bl[p], bBaseL + (uint32_t)(p * 16 * GK_RSB) + ko);
            }
#pragma unroll
            for (int mi = 0; mi < 4; mi++)
#pragma unroll
                for (int ni = 0; ni < 4; ni++) {
                    const uint32_t* bhf = &bh[ni >> 1][(ni & 1) * 2];
                    const uint32_t* blf = &bl[ni >> 1][(ni & 1) * 2];
                    mma_bf16(acc[mi][ni], ah[mi], bhf);
                    mma_bf16(acc[mi][ni], ah[mi], blf);
                    mma_bf16(acc[mi][ni], al[mi], bhf);
                }
        }
        __syncthreads();
        if (++stg_idx == GK_STAGES) stg_idx = 0;
    }

    // epilogue (no bias, no hs): c0,c1 at (row=tq, col=tp*2), c2,c3 at row+8
#pragma unroll
    for (int mi = 0; mi < 4; mi++) {
        const int gr0 = rowBase + m0 + mi * 16 + tq;
        const int gr1 = gr0 + 8;
#pragma unroll
        for (int ni = 0; ni < 4; ni++) {
            const int gc = colBase + n0 + ni * 8 + tp * 2;
            if (EPI1) {
                __nv_bfloat16 h0, h1, h2, h3, l0, l1, l2, l3;
                split2(acc[mi][ni][0], h0, l0); split2(acc[mi][ni][1], h1, l1);
                split2(acc[mi][ni][2], h2, l2); split2(acc[mi][ni][3], h3, l3);
                const size_t o0 = ((size_t)gr0 * PI + gc) >> 1;
                const size_t o1 = ((size_t)gr1 * PI + gc) >> 1;
                ((__nv_bfloat162*)g_T_hi)[o0] = __nv_bfloat162(h0, h1);
                ((__nv_bfloat162*)g_T_lo)[o0] = __nv_bfloat162(l0, l1);
                ((__nv_bfloat162*)g_T_hi)[o1] = __nv_bfloat162(h2, h3);
                ((__nv_bfloat162*)g_T_lo)[o1] = __nv_bfloat162(l2, l3);
            } else {
                float2 w0 = {acc[mi][ni][0], acc[mi][ni][1]};
                float2 w1 = {acc[mi][ni][2], acc[mi][ni][3]};
                *(float2*)(g_E + (size_t)gr0 * PD + gc) = w0;
                *(float2*)(g_E + (size_t)gr1 * PD + gc) = w1;
            }
        }
    }
}

// ---------------------------------------------------------------------------
// Softmax over L + alpha write + z reduce. Block per (b, 64-wide d-chunk).
// 224 threads = 28 row-groups x 8 col-groups; 7x8 elements per thread.
// ---------------------------------------------------------------------------
__global__ __launch_bounds__(224) void softmax_kernel(const float* __restrict__ fv,
                                                      float* __restrict__ z,
                                                      float* __restrict__ alpha) {
    __shared__ float red[28 * 64];
    __shared__ float colmax[64];
    __shared__ float colsum[64];

    const int tid = threadIdx.x;
    const int tc = tid & 7;
    const int tr = tid >> 3;
    const int b = blockIdx.y;
    const int dbase = blockIdx.x * 64;

    float acc[7][8];
#pragma unroll
    for (int r = 0; r < 7; r++) {
        const int l = tr * 7 + r;
        const size_t base = ((size_t)b * PL + l) * PD + dbase + tc * 8;
        float4 e0 = *(const float4*)(g_E + base);
        float4 e1 = *(const float4*)(g_E + base + 4);
        acc[r][0] = e0.x; acc[r][1] = e0.y; acc[r][2] = e0.z; acc[r][3] = e0.w;
        acc[r][4] = e1.x; acc[r][5] = e1.y; acc[r][6] = e1.z; acc[r][7] = e1.w;
    }

    float lm[8];
#pragma unroll
    for (int j = 0; j < 8; j++) {
        float m = acc[0][j];
#pragma unroll
        for (int r = 1; r < 7; r++) m = fmaxf(m, acc[r][j]);
        lm[j] = m;
    }
#pragma unroll
    for (int j = 0; j < 8; j++) red[tr * 64 + tc * 8 + j] = lm[j];
    __syncthreads();
    if (tid < 64) {
        float m = -CUDART_INF_F;
#pragma unroll
        for (int t = 0; t < 28; t++) m = fmaxf(m, red[t * 64 + tid]);
        colmax[tid] = m;
    }
    __syncthreads();
    float cm[8];
#pragma unroll
    for (int j = 0; j < 8; j++) cm[j] = colmax[tc * 8 + j];

    float ls[8];
#pragma unroll
    for (int j = 0; j < 8; j++) ls[j] = 0.0f;
#pragma unroll
    for (int r = 0; r < 7; r++)
#pragma unroll
        for (int j = 0; j < 8; j++) {
            float e = __expf(acc[r][j] - cm[j]);
            acc[r][j] = e;
            ls[j] += e;
        }
#pragma unroll
    for (int j = 0; j < 8; j++) red[tr * 64 + tc * 8 + j] = ls[j];
    __syncthreads();
    if (tid < 64) {
        float s = 0.0f;
#pragma unroll
        for (int t = 0; t < 28; t++) s += red[t * 64 + tid];
        colsum[tid] = s;
    }
    __syncthreads();
    float inv[8];
#pragma unroll
    for (int j = 0; j < 8; j++) inv[j] = 1.0f / colsum[tc * 8 + j];

    float zp[8];
#pragma unroll
    for (int j = 0; j < 8; j++) zp[j] = 0.0f;
#pragma unroll
    for (int r = 0; r < 7; r++) {
        const int l = tr * 7 + r;
        const size_t base = ((size_t)b * PL + l) * PD + dbase + tc * 8;
        float4 f0 = *(const float4*)(fv + base);
        float4 f1 = *(const float4*)(fv + base + 4);
        float a0 = acc[r][0] * inv[0], a1 = acc[r][1] * inv[1];
        float a2 = acc[r][2] * inv[2], a3 = acc[r][3] * inv[3];
        float a4 = acc[r][4] * inv[4], a5 = acc[r][5] * inv[5];
        float a6 = acc[r][6] * inv[6], a7 = acc[r][7] * inv[7];
        float4 o0 = {a0, a1, a2, a3};
        float4 o1 = {a4, a5, a6, a7};
        *(float4*)(alpha + base) = o0;
        *(float4*)(alpha + base + 4) = o1;
        zp[0] = fmaf(a0, f0.x, zp[0]); zp[1] = fmaf(a1, f0.y, zp[1]);
        zp[2] = fmaf(a2, f0.z, zp[2]); zp[3] = fmaf(a3, f0.w, zp[3]);
        zp[4] = fmaf(a4, f1.x, zp[4]); zp[5] = fmaf(a5, f1.y, zp[5]);
        zp[6] = fmaf(a6, f1.z, zp[6]); zp[7] = fmaf(a7, f1.w, zp[7]);
    }
#pragma unroll
    for (int j = 0; j < 8; j++) red[tr * 64 + tc * 8 + j] = zp[j];
    __syncthreads();
    if (tid < 64) {
        float s = 0.0f;
#pragma unroll
        for (int t = 0; t < 28; t++) s += red[t * 64 + tid];
        z[b * PD + dbase + tid] = s;
    }
}

// ---------------------------------------------------------------------------
// Launch
// ---------------------------------------------------------------------------
extern "C" void kernel_launch(void* const* d_in, const int* in_sizes, int n_in,
                              void* d_out, int out_size) {
    const float* fv     = (const float*)d_in[0];
    const float* W_f    = (const float*)d_in[2];
    const float* W_a    = (const float*)d_in[6];

    float* out   = (float*)d_out;
    float* z     = out;
    float* alpha = out + (size_t)PB * PD;

    cudaFuncSetAttribute(gemm_kernel<PD / GK_BK, true>,
                         cudaFuncAttributeMaxDynamicSharedMemorySize, GEMM_SMEM);
    cudaFuncSetAttribute(gemm_kernel<PI / GK_BK, false>,
                         cudaFuncAttributeMaxDynamicSharedMemorySize, GEMM_SMEM);

    __nv_bfloat16 *wft_hi, *wft_lo, *wat_hi, *wat_lo;
    cudaGetSymbolAddress((void**)&wft_hi, g_Wft_hi);
    cudaGetSymbolAddress((void**)&wft_lo, g_Wft_lo);
    cudaGetSymbolAddress((void**)&wat_hi, g_Wat_hi);
    cudaGetSymbolAddress((void**)&wat_lo, g_Wat_lo);

    // 1) conversions
    {
        size_t n4 = (size_t)PM * PD / 4;
        int blocks = (int)((n4 + 255) / 256);
        split_fv_kernel<<<blocks, 256>>>(fv);
    }
    tsplit_kernel<<<dim3(PI / 32, PD / 32), dim3(32, 8)>>>(W_f, wft_hi, wft_lo, PD, PI);
    tsplit_kernel<<<dim3(PD / 32, PI / 32), dim3(32, 8)>>>(W_a, wat_hi, wat_lo, PI, PD);

    // 2) GEMM1: T = fv @ W_f   (M=12544, N=512, K=2048)
    gemm_kernel<PD / GK_BK, true>
        <<<dim3(PI / GK_BN, PM / GK_BM), 256, GEMM_SMEM>>>();

    // 3) GEMM2: E = T @ W_a    (M=12544, N=2048, K=512)
    gemm_kernel<PI / GK_BK, false>
        <<<dim3(PD / GK_BN, PM / GK_BM), 256, GEMM_SMEM>>>();

    // 4) softmax + alpha + z
    softmax_kernel<<<dim3(PD / 64, PB), 224>>>(fv, z, alpha);
}